// round 15
// baseline (speedup 1.0000x reference)
#include <cuda_runtime.h>
#include <cuda_fp16.h>

#define BATCH 4
#define HDIM 384
#define WDIM 384
#define NPIX (BATCH*HDIM*WDIM)

// fp16 q/k/v scratch
__device__ __half g_q[NPIX*64];
__device__ __half g_k[NPIX*64];
__device__ __half g_v[NPIX*64];
// fp16 weights, B-operand layout [n][k] padded to 72
__device__ __half g_wqkv_h[192*72];
__device__ __half g_ff1n[128*72];
__device__ __half g_ff2n[2*64*72];
__device__ __half g_wfusen[64*72];

__device__ __forceinline__ void mma_f16(float* d,
    unsigned a0, unsigned a1, unsigned a2, unsigned a3,
    unsigned b0, unsigned b1)
{
    asm volatile("mma.sync.aligned.m16n8k16.row.col.f32.f16.f16.f32 "
        "{%0,%1,%2,%3}, {%4,%5,%6,%7}, {%8,%9}, {%0,%1,%2,%3};"
        : "+f"(d[0]), "+f"(d[1]), "+f"(d[2]), "+f"(d[3])
        : "r"(a0), "r"(a1), "r"(a2), "r"(a3), "r"(b0), "r"(b1));
}

__device__ __forceinline__ unsigned sptr(const void* p) {
    return (unsigned)__cvta_generic_to_shared((void*)p);
}
#define CP16(dst, src, sz) \
    asm volatile("cp.async.cg.shared.global [%0], [%1], 16, %2;" \
                 :: "r"(dst), "l"(src), "r"(sz))
#define CP_COMMIT asm volatile("cp.async.commit_group;" ::: "memory")
#define CP_WAIT0  asm volatile("cp.async.wait_group 0;"  ::: "memory")
#define CP_WAIT1  asm volatile("cp.async.wait_group 1;"  ::: "memory")

// ---------------------------------------------------------------------------
// One-time weight prep: row-per-block decode
// ---------------------------------------------------------------------------
__global__ void __launch_bounds__(128) cvt_weights_kernel(
    const float* __restrict__ wq, const float* __restrict__ wk,
    const float* __restrict__ wv, const float* __restrict__ ff1_w,
    const float* __restrict__ ff2_w, const float* __restrict__ w_fuse)
{
    int r = blockIdx.x, k = threadIdx.x;
    if (k >= 72) return;
    float v = 0.f;
    __half* dst;
    if (r < 192) {
        if (k < 64) {
            if (r < 64)       v = wq[k*64 + r];
            else if (r < 128) v = wk[k*64 + r - 64];
            else              v = wv[k*64 + r - 128];
        }
        dst = g_wqkv_h + r*72;
    } else if (r < 320) {
        int n = r - 192;
        if (k < 64) v = ff1_w[k*128 + n];
        dst = g_ff1n + n*72;
    } else if (r < 448) {
        int q2 = r - 320;
        int P = q2 >> 6, n = q2 & 63;
        if (k < 64) v = ff2_w[(P*64 + k)*64 + n];
        dst = g_ff2n + q2*72;
    } else {
        int n = r - 448;
        if (k < 64) v = w_fuse[k*64 + n];
        dst = g_wfusen + n*72;
    }
    dst[k] = __float2half_rn(v);
}

// ---------------------------------------------------------------------------
// Kernel A: persistent qkv projection (unchanged).
// ---------------------------------------------------------------------------
#define NTILES 9216

__global__ void __launch_bounds__(256,2) qkv_kernel(const float* __restrict__ x)
{
    extern __shared__ char smc[];
    __half* ws  = (__half*)smc;
    __half* xs0 = (__half*)(smc + 27648);
    __half* xs1 = (__half*)(smc + 36864);
    const int tid = threadIdx.x;

    {
        const char* src = (const char*)g_wqkv_h;
        unsigned base = sptr(ws);
        for (int i = tid; i < 1728; i += 256) CP16(base + i*16, src + i*16, 16);
        CP_COMMIT;
    }

    int tile = blockIdx.x;
    const int stride = gridDim.x;

    float4 r[4];
    {
        const float4* xg = (const float4*)(x + (long)tile*64*64);
        #pragma unroll
        for (int j = 0; j < 4; j++) r[j] = xg[tid + 256*j];
    }
    CP_WAIT0;
    #pragma unroll
    for (int j = 0; j < 4; j++) {
        int i = tid + 256*j;
        int m = i >> 4, c4 = i & 15;
        int col = (4*c4) ^ ((m & 3) << 4);
        __half2* d = (__half2*)&xs0[m*72 + col];
        d[0] = __floats2half2_rn(r[j].x, r[j].y);
        d[1] = __floats2half2_rn(r[j].z, r[j].w);
    }
    __syncthreads();

    const int wid = tid >> 5, lane = tid & 31;
    const int gr = lane >> 2, tg = lane & 3;
    const int m0 = (wid >> 1) * 16;
    const int nb = (wid & 1) * 96;
    const unsigned* wsU = (const unsigned*)ws;
    const int mr = m0 + gr;
    const int sw = (mr & 3) << 3;

    int cur = 0;
    while (true) {
        int ntile = tile + stride;
        bool more = ntile < NTILES;
        if (more) {
            const float4* xg = (const float4*)(x + (long)ntile*64*64);
            #pragma unroll
            for (int j = 0; j < 4; j++) r[j] = xg[tid + 256*j];
        }

        const unsigned* xsU = (const unsigned*)(cur ? xs1 : xs0);
        float d[12][4];
        #pragma unroll
        for (int j = 0; j < 12; j++)
            #pragma unroll
            for (int c = 0; c < 4; c++) d[j][c] = 0.f;

        #pragma unroll
        for (int k0 = 0; k0 < 64; k0 += 16) {
            const int kc = k0 >> 1;
            unsigned a0 = xsU[mr*36       + ((kc+tg)   ^ sw)];
            unsigned a1 = xsU[mr*36 + 288 + ((kc+tg)   ^ sw)];
            unsigned a2 = xsU[mr*36       + ((kc+tg+4) ^ sw)];
            unsigned a3 = xsU[mr*36 + 288 + ((kc+tg+4) ^ sw)];
            #pragma unroll
            for (int j = 0; j < 12; j++) {
                int nn = nb + j*8;
                unsigned b0 = wsU[(nn+gr)*36 + kc+tg];
                unsigned b1 = wsU[(nn+gr)*36 + kc+tg+4];
                mma_f16(d[j], a0, a1, a2, a3, b0, b1);
            }
        }

        #pragma unroll
        for (int j = 0; j < 12; j++) {
            int n = nb + j*8 + 2*tg;
            __half* dst; int nn;
            if (n < 64)       { dst = g_q; nn = n; }
            else if (n < 128) { dst = g_k; nn = n - 64; }
            else              { dst = g_v; nn = n - 128; }
            long m = (long)tile*64 + mr;
            *(__half2*)&dst[m*64 + nn]     = __floats2half2_rn(d[j][0], d[j][1]);
            *(__half2*)&dst[(m+8)*64 + nn] = __floats2half2_rn(d[j][2], d[j][3]);
        }
        if (!more) break;
        tile = ntile;
        __half* xsn = cur ? xs0 : xs1;
        #pragma unroll
        for (int j = 0; j < 4; j++) {
            int i = tid + 256*j;
            int m = i >> 4, c4 = i & 15;
            int col = (4*c4) ^ ((m & 3) << 4);
            __half2* dd = (__half2*)&xsn[m*72 + col];
            dd[0] = __floats2half2_rn(r[j].x, r[j].y);
            dd[1] = __floats2half2_rn(r[j].z, r[j].w);
        }
        cur ^= 1;
        __syncthreads();
    }
}

// ---------------------------------------------------------------------------
// Shared 128x32 (K=64) fp16 MMA GEMM body
// ---------------------------------------------------------------------------
__device__ __forceinline__ void gemm_64(const unsigned* aU, const unsigned* bU,
    int m0, int gr, int tg, int wn, float d[8][4])
{
    #pragma unroll
    for (int k0 = 0; k0 < 64; k0 += 16) {
        const int kc = k0 >> 1;
        unsigned a[2][4];
        #pragma unroll
        for (int t = 0; t < 2; t++) {
            int mr = m0 + 16*t + gr;
            int sw = (mr & 3) << 3;
            int base = mr*36;
            a[t][0] = aU[base       + ((kc+tg)   ^ sw)];
            a[t][1] = aU[base + 288 + ((kc+tg)   ^ sw)];
            a[t][2] = aU[base       + ((kc+tg+4) ^ sw)];
            a[t][3] = aU[base + 288 + ((kc+tg+4) ^ sw)];
        }
        #pragma unroll
        for (int j = 0; j < 4; j++) {
            int nn = wn*32 + j*8;
            unsigned b0 = bU[(nn+gr)*36 + kc+tg];
            unsigned b1 = bU[(nn+gr)*36 + kc+tg+4];
            #pragma unroll
            for (int t = 0; t < 2; t++)
                mma_f16(d[t*4+j], a[t][0], a[t][1], a[t][2], a[t][3], b0, b1);
        }
    }
}

// ---------------------------------------------------------------------------
// Kernel B. smem bytes (70016 total; 3 blocks/SM = 210 KB):
//   [0,38016)      halo half [264][72] (swizzled)
//     aliases: s_w [0,9216) | s_h [9216,27648)
//   [38016,40064)  s_sums f32 [128][4]
//   [40064,58496)  s_o half [128][72] (swizzled)
//   [58496,60800)  s_m fp32 (576)
//   [60800,70016)  s_w1 half [64][72]  (dedicated; prefetched ff1/fuse)
// ---------------------------------------------------------------------------
#define SMB_BYTES 70016

__global__ void __launch_bounds__(256,3) attn_ffn_kernel(
    const float* __restrict__ x,
    const float* __restrict__ ln1_g, const float* __restrict__ ln1_b,
    const float* __restrict__ ff1_b,
    const float* __restrict__ ff2_b,
    const float* __restrict__ ln2_g, const float* __restrict__ ln2_b,
    const float* __restrict__ bn_g, const float* __restrict__ bn_b,
    const float* __restrict__ bn_mean, const float* __restrict__ bn_var,
    float* __restrict__ out)
{
    extern __shared__ char smc[];
    __half* s_halo = (__half*)smc;              // [264][72]
    __half* s_w    = (__half*)smc;              // [64][72]
    __half* s_h    = (__half*)(smc + 9216);     // [128][72]
    float*  s_sums = (float*)(smc + 38016);     // [128][4]
    __half* s_o    = (__half*)(smc + 40064);    // [128][72]
    float*  s_m    = (float*)(smc + 58496);
    __half* s_w1   = (__half*)(smc + 60800);    // [64][72]

    const int tid = threadIdx.x;
    const int b  = blockIdx.z;
    const int y0 = blockIdx.y * 2;
    const int c0 = blockIdx.x * 64;

    // ---- issue k-halo (group 1) ----
    #pragma unroll
    for (int r = 0; r < 4; r++) {
        const int gy = y0 + r - 1;
        const bool rowok = (unsigned)gy < HDIM;
        const __half* src = g_k + (((long)b*HDIM + gy)*WDIM + c0 - 1)*64;
        for (int idx = tid; idx < 528; idx += 256) {
            int j = idx >> 3, c8 = idx & 7;
            int gx = c0 + j - 1;
            int row = r*66 + j;
            int off = row*72 + ((c8*8) ^ ((row & 3) << 4));
            int sz = (rowok && (unsigned)gx < WDIM) ? 16 : 0;
            CP16(sptr(s_halo + off), src + j*64 + c8*8, sz);
        }
    }
    CP_COMMIT;
    {   // ---- prefetch ff1[P0] into s_w1 (group 2) ----
        const char* src = (const char*)g_ff1n;
        unsigned base = sptr(s_w1);
        for (int i = tid; i < 576; i += 256) CP16(base + i*16, src + i*16, 16);
        CP_COMMIT;
    }

    if (tid < 64) {
        s_m[tid]        = ln1_g[tid];
        s_m[64 + tid]   = ln1_b[tid];
        s_m[128 + tid]  = ln2_g[tid];
        s_m[192 + tid]  = ln2_b[tid];
        s_m[384 + tid]  = ff2_b[tid];
        float sc = bn_g[tid] * rsqrtf(bn_var[tid] + 1e-3f);
        s_m[448 + tid]  = sc;
        s_m[512 + tid]  = bn_b[tid] - bn_mean[tid]*sc;
    } else if (tid < 192) {
        s_m[256 + (tid - 64)] = ff1_b[tid - 64];
    }

    const int p  = tid >> 2;
    const int hd = tid & 3;
    const long base0 = (((long)b*HDIM + y0)*WDIM + c0 + p)*64;
    const long base1 = base0 + WDIM*64;

    union HU { uint4 u[2]; __half2 h[8]; };
    HU q0h, q1h;
    q0h.u[0] = *(const uint4*)(g_q + base0 + hd*16);
    q0h.u[1] = *(const uint4*)(g_q + base0 + hd*16 + 8);
    q1h.u[0] = *(const uint4*)(g_q + base1 + hd*16);
    q1h.u[1] = *(const uint4*)(g_q + base1 + hd*16 + 8);
    CP_WAIT1;            // k-halo done (ff1 may still fly)
    __syncthreads();

    // ---- scores: half2 accumulation ----
    float s0[9], s1[9];
    #pragma unroll
    for (int r = 0; r < 4; r++) {
        #pragma unroll
        for (int dx = 0; dx < 3; dx++) {
            int row = r*66 + p + dx;
            const __half* kp = &s_halo[row*72 + ((hd ^ (row & 3)) << 4)];
            HU bk;
            bk.u[0] = *(const uint4*)kp;
            bk.u[1] = *(const uint4*)(kp + 8);
            if (r < 3) {
                __half2 acc = __float2half2_rn(0.f);
                #pragma unroll
                for (int i = 0; i < 8; i++) acc = __hfma2(q0h.h[i], bk.h[i], acc);
                float2 f = __half22float2(acc);
                s0[r*3 + dx] = (f.x + f.y) * 0.25f;
            }
            if (r > 0) {
                __half2 acc = __float2half2_rn(0.f);
                #pragma unroll
                for (int i = 0; i < 8; i++) acc = __hfma2(q1h.h[i], bk.h[i], acc);
                float2 f = __half22float2(acc);
                s1[(r-1)*3 + dx] = (f.x + f.y) * 0.25f;
            }
        }
    }
    float sum0 = 0.f, sum1 = 0.f;
    #pragma unroll
    for (int o = 0; o < 9; o++) {
        s0[o] = __expf(s0[o]); sum0 += s0[o];
        s1[o] = __expf(s1[o]); sum1 += s1[o];
    }
    const float si0 = 1.f/sum0, si1 = 1.f/sum1;
    #pragma unroll
    for (int o = 0; o < 9; o++) { s0[o] *= si0; s1[o] *= si1; }

    __syncthreads();   // k-halo reads done

    // ---- issue v-halo (group) ----
    #pragma unroll
    for (int r = 0; r < 4; r++) {
        const int gy = y0 + r - 1;
        const bool rowok = (unsigned)gy < HDIM;
        const __half* src = g_v + (((long)b*HDIM + gy)*WDIM + c0 - 1)*64;
        for (int idx = tid; idx < 528; idx += 256) {
            int j = idx >> 3, c8 = idx & 7;
            int gx = c0 + j - 1;
            int row = r*66 + j;
            int off = row*72 + ((c8*8) ^ ((row & 3) << 4));
            int sz = (rowok && (unsigned)gx < WDIM) ? 16 : 0;
            CP16(sptr(s_halo + off), src + j*64 + c8*8, sz);
        }
    }
    CP_COMMIT;

    float xr0[16], xr1[16];
    #pragma unroll
    for (int i = 0; i < 4; i++) {
        *(float4*)&xr0[4*i] = *(const float4*)(x + base0 + hd*16 + 4*i);
        *(float4*)&xr1[4*i] = *(const float4*)(x + base1 + hd*16 + 4*i);
    }
    CP_WAIT0;           // v-halo + ff1P0 done
    __syncthreads();

    // ---- weighted v sums: half2 ----
    __half2 a0h[8], a1h[8];
    #pragma unroll
    for (int i = 0; i < 8; i++) { a0h[i] = __float2half2_rn(0.f); a1h[i] = __float2half2_rn(0.f); }
    #pragma unroll
    for (int r = 0; r < 4; r++) {
        #pragma unroll
        for (int dx = 0; dx < 3; dx++) {
            int row = r*66 + p + dx;
            const __half* vp = &s_halo[row*72 + ((hd ^ (row & 3)) << 4)];
            HU bv;
            bv.u[0] = *(const uint4*)vp;
            bv.u[1] = *(const uint4*)(vp + 8);
            if (r < 3) {
                __half2 w = __half2half2(__float2half_rn(s0[r*3 + dx]));
                #pragma unroll
                for (int i = 0; i < 8; i++) a0h[i] = __hfma2(w, bv.h[i], a0h[i]);
            }
            if (r > 0) {
                __half2 w = __half2half2(__float2half_rn(s1[(r-1)*3 + dx]));
                #pragma unroll
                for (int i = 0; i < 8; i++) a1h[i] = __hfma2(w, bv.h[i], a1h[i]);
            }
        }
    }

    // ---- LN1 (+residual) fp32; fp16 into swizzled s_o ----
    #pragma unroll
    for (int rr = 0; rr < 2; rr++) {
        __half2* ah = rr ? a1h : a0h;
        float* xv = rr ? xr1 : xr0;
        float av[16];
        #pragma unroll
        for (int i = 0; i < 8; i++) {
            float2 f = __half22float2(ah[i]);
            av[2*i] = f.x; av[2*i+1] = f.y;
        }
        float m1 = 0.f, m2 = 0.f;
        #pragma unroll
        for (int dd = 0; dd < 16; dd++) {
            av[dd] += xv[dd];
            m1 += av[dd];
            m2 = fmaf(av[dd], av[dd], m2);
        }
        m1 += __shfl_xor_sync(0xffffffff, m1, 1);
        m2 += __shfl_xor_sync(0xffffffff, m2, 1);
        m1 += __shfl_xor_sync(0xffffffff, m1, 2);
        m2 += __shfl_xor_sync(0xffffffff, m2, 2);
        const float mean = m1 * (1.f/64.f);
        const float var  = m2 * (1.f/64.f) - mean*mean;
        const float rstd = rsqrtf(var + 1e-3f);
        int row = rr*64 + p;
        __half2* dst = (__half2*)&s_o[row*72 + ((hd ^ (row & 3)) << 4)];
        #pragma unroll
        for (int i = 0; i < 4; i++) {
            const int c = hd*16 + 4*i;
            float w0 = (av[4*i+0] - mean)*rstd*s_m[c+0] + s_m[64+c+0];
            float w1 = (av[4*i+1] - mean)*rstd*s_m[c+1] + s_m[64+c+1];
            float w2 = (av[4*i+2] - mean)*rstd*s_m[c+2] + s_m[64+c+2];
            float w3 = (av[4*i+3] - mean)*rstd*s_m[c+3] + s_m[64+c+3];
            dst[2*i]   = __floats2half2_rn(w0, w1);
            dst[2*i+1] = __floats2half2_rn(w2, w3);
        }
    }
    __syncthreads();   // halo dead (s_w/s_h usable); LN1 visible

    const int wid = tid >> 5, lane = tid & 31;
    const int gr = lane >> 2, tg = lane & 3;
    const int m0 = (wid >> 1) * 32;
    const int wn = wid & 1;
    const unsigned* soU  = (const unsigned*)s_o;
    const unsigned* shU  = (const unsigned*)s_h;
    const unsigned* swU  = (const unsigned*)s_w;
    const unsigned* sw1U = (const unsigned*)s_w1;

    // ---- pipelined FFN: every stage hides behind a GEMM ----
    float d2[8][4];
    #pragma unroll
    for (int j = 0; j < 8; j++)
        #pragma unroll
        for (int c = 0; c < 4; c++) d2[j][c] = 0.f;

    {   // issue ff2[P0] -> s_w (overlaps GEMM1-P0)
        const char* src = (const char*)g_ff2n;
        unsigned base = sptr(s_w);
        for (int i = tid; i < 576; i += 256) CP16(base + i*16, src + i*16, 16);
        CP_COMMIT;
    }
    float d1[8][4];
    #pragma unroll
    for (int j = 0; j < 8; j++)
        #pragma unroll
        for (int c = 0; c < 4; c++) d1[j][c] = 0.f;
    gemm_64(soU, sw1U, m0, gr, tg, wn, d1);          // GEMM1-P0 (prefetched ff1P0)
    // h-writes P0 (s_h free since halo-dead sync; no barrier needed)
    #pragma unroll
    for (int t = 0; t < 2; t++) {
        #pragma unroll
        for (int j = 0; j < 4; j++) {
            int nl = wn*32 + j*8 + 2*tg;
            int mr = m0 + 16*t + gr;
            float bb0 = s_m[256 + nl], bb1 = s_m[256 + nl + 1];
            int sw4 = (mr & 3) << 4;
            *(__half2*)&s_h[mr*72 + (nl ^ sw4)] = __floats2half2_rn(
                fmaxf(d1[t*4+j][0] + bb0, 0.f), fmaxf(d1[t*4+j][1] + bb1, 0.f));
            *(__half2*)&s_h[(mr+8)*72 + (nl ^ sw4)] = __floats2half2_rn(
                fmaxf(d1[t*4+j][2] + bb0, 0.f), fmaxf(d1[t*4+j][3] + bb1, 0.f));
        }
    }
    CP_WAIT0;          // ff2P0 landed (hidden behind GEMM1-P0)
    __syncthreads();   // publish ff2P0 + h; retire GEMM1-P0 reads of s_w1

    {   // issue ff1[P1] -> s_w1 (overlaps GEMM2-P0)
        const char* src = (const char*)g_ff1n + 9216;
        unsigned base = sptr(s_w1);
        for (int i = tid; i < 576; i += 256) CP16(base + i*16, src + i*16, 16);
        CP_COMMIT;
    }
    gemm_64(shU, swU, m0, gr, tg, wn, d2);           // GEMM2-P0
    CP_WAIT0;          // ff1P1 landed
    __syncthreads();   // publish ff1P1; retire GEMM2-P0 reads of s_w/s_h

    {   // issue ff2[P1] -> s_w (overlaps GEMM1-P1)
        const char* src = (const char*)g_ff2n + 9216;
        unsigned base = sptr(s_w);
        for (int i = tid; i < 576; i += 256) CP16(base + i*16, src + i*16, 16);
        CP_COMMIT;
    }
    #pragma unroll
    for (int j = 0; j < 8; j++)
        #pragma unroll
        for (int c = 0; c < 4; c++) d1[j][c] = 0.f;
    gemm_64(soU, sw1U, m0, gr, tg, wn, d1);          // GEMM1-P1
    // h-writes P1
    #pragma unroll
    for (int t = 0; t < 2; t++) {
        #pragma unroll
        for (int j = 0; j < 4; j++) {
            int nl = wn*32 + j*8 + 2*tg;
            int ng = 64 + nl;
            int mr = m0 + 16*t + gr;
            float bb0 = s_m[256 + ng], bb1 = s_m[256 + ng + 1];
            int sw4 = (mr & 3) << 4;
            *(__half2*)&s_h[mr*72 + (nl ^ sw4)] = __floats2half2_rn(
                fmaxf(d1[t*4+j][0] + bb0, 0.f), fmaxf(d1[t*4+j][1] + bb1, 0.f));
            *(__half2*)&s_h[(mr+8)*72 + (nl ^ sw4)] = __floats2half2_rn(
                fmaxf(d1[t*4+j][2] + bb0, 0.f), fmaxf(d1[t*4+j][3] + bb1, 0.f));
        }
    }
    CP_WAIT0;          // ff2P1 landed
    __syncthreads();   // publish ff2P1 + hP1; retire GEMM1-P1 reads of s_w1

    {   // issue fuse -> s_w1 (overlaps GEMM2-P1 + epilogue)
        const char* src = (const char*)g_wfusen;
        unsigned base = sptr(s_w1);
        for (int i = tid; i < 576; i += 256) CP16(base + i*16, src + i*16, 16);
        CP_COMMIT;
    }
    gemm_64(shU, swU, m0, gr, tg, wn, d2);           // GEMM2-P1

    // ---- epilogue + warp-level LN2 ----
    float rs[4], rq[4];
    #pragma unroll
    for (int i = 0; i < 4; i++) { rs[i] = 0.f; rq[i] = 0.f; }
    #pragma unroll
    for (int t = 0; t < 2; t++) {
        #pragma unroll
        for (int j = 0; j < 4; j++) {
            int n = wn*32 + j*8 + 2*tg;
            int mr = m0 + 16*t + gr;
            int sw4 = (mr & 3) << 4;
            float bb0 = s_m[384 + n], bb1 = s_m[384 + n + 1];
            float2 o0 = __half22float2(*(__half2*)&s_o[mr*72 + (n ^ sw4)]);
            float2 o1 = __half22float2(*(__half2*)&s_o[(mr+8)*72 + (n ^ sw4)]);
            float v0 = o0.x + d2[t*4+j][0] + bb0;
            float v1 = o0.y + d2[t*4+j][1] + bb1;
            float v2 = o1.x + d2[t*4+j][2] + bb0;
            float v3 = o1.y + d2[t*4+j][3] + bb1;
            d2[t*4+j][0] = v0; d2[t*4+j][1] = v1;
            d2[t*4+j][2] = v2; d2[t*4+j][3] = v3;
            rs[2*t]   += v0 + v1;
            rq[2*t]   = fmaf(v0, v0, fmaf(v1, v1, rq[2*t]));
            rs[2*t+1] += v2 + v3;
            rq[2*t+1] = fmaf(v2, v2, fmaf(v3, v3, rq[2*t+1]));
        }
    }
    #pragma unroll
    for (int i = 0; i < 4; i++) {
        rs[i] += __shfl_xor_sync(0xffffffff, rs[i], 1);
        rq[i] += __shfl_xor_sync(0xffffffff, rq[i], 1);
        rs[i] += __shfl_xor_sync(0xffffffff, rs[i], 2);
        rq[i] += __shfl_xor_sync(0xffffffff, rq[i], 2);
    }
    if (tg == 0) {
        #pragma unroll
        for (int i = 0; i < 4; i++) {
            int row = m0 + 16*(i >> 1) + 8*(i & 1) + gr;
            *(float2*)&s_sums[row*4 + wn*2] = make_float2(rs[i], rq[i]);
        }
    }
    CP_WAIT0;          // fuse landed (hidden behind GEMM2-P1 + epilogue)
    __syncthreads();   // publish s_sums + fuse

    float mean[4], rstd[4];
    #pragma unroll
    for (int i = 0; i < 4; i++) {
        int row = m0 + 16*(i >> 1) + 8*(i & 1) + gr;
        float4 s4 = *(const float4*)&s_sums[row*4];
        float mn = (s4.x + s4.z) * (1.f/64.f);
        float vr = (s4.y + s4.w) * (1.f/64.f) - mn*mn;
        mean[i] = mn;
        rstd[i] = rsqrtf(vr + 1e-3f);
    }
    #pragma unroll
    for (int t = 0; t < 2; t++) {
        #pragma unroll
        for (int j = 0; j < 4; j++) {
            int n = wn*32 + j*8 + 2*tg;
            int mr = m0 + 16*t + gr;
            int sw4 = (mr & 3) << 4;
            float g0 = s_m[128 + n], g1 = s_m[128 + n + 1];
            float e0 = s_m[192 + n], e1 = s_m[192 + n + 1];
            int i0 = 2*t, i1 = 2*t + 1;
            *(__half2*)&s_o[mr*72 + (n ^ sw4)] = __floats2half2_rn(
                (d2[t*4+j][0] - mean[i0])*rstd[i0]*g0 + e0,
                (d2[t*4+j][1] - mean[i0])*rstd[i0]*g1 + e1);
            *(__half2*)&s_o[(mr+8)*72 + (n ^ sw4)] = __floats2half2_rn(
                (d2[t*4+j][2] - mean[i1])*rstd[i1]*g0 + e0,
                (d2[t*4+j][3] - mean[i1])*rstd[i1]*g1 + e1);
        }
    }
    __syncthreads();   // LN2 visible (GEMM3 A-rows span both wn warps' writes)

    // ---- GEMM3: fuse conv + BN + relu, direct global store ----
    {
        float d3[8][4];
        #pragma unroll
        for (int j = 0; j < 8; j++)
            #pragma unroll
            for (int c = 0; c < 4; c++) d3[j][c] = 0.f;
        gemm_64(soU, sw1U, m0, gr, tg, wn, d3);
        #pragma unroll
        for (int t = 0; t < 2; t++) {
            #pragma unroll
            for (int j = 0; j < 4; j++) {
                int n = wn*32 + j*8 + 2*tg;
                int mr = m0 + 16*t + gr;
                int ry = mr >> 6, mx = mr & 63;
                float sc0 = s_m[448 + n], sc1 = s_m[448 + n + 1];
                float sh0 = s_m[512 + n], sh1 = s_m[512 + n + 1];
                float* ob0 = out + ((b*HDIM + y0 + ry)*WDIM + c0 + mx)*64;
                float* ob1 = out + ((b*HDIM + y0 + ry)*WDIM + c0 + mx + 8)*64;
                *(float2*)&ob0[n] = make_float2(
                    fmaxf(d3[t*4+j][0]*sc0 + sh0, 0.f), fmaxf(d3[t*4+j][1]*sc1 + sh1, 0.f));
                *(float2*)&ob1[n] = make_float2(
                    fmaxf(d3[t*4+j][2]*sc0 + sh0, 0.f), fmaxf(d3[t*4+j][3]*sc1 + sh1, 0.f));
            }
        }
    }
}

extern "C" void kernel_launch(void* const* d_in, const int* in_sizes, int n_in,
                              void* d_out, int out_size)
{
    const float* x      = (const float*)d_in[0];
    const float* wq     = (const float*)d_in[1];
    const float* wk     = (const float*)d_in[2];
    const float* wv     = (const float*)d_in[3];
    const float* ln1_g  = (const float*)d_in[4];
    const float* ln1_b  = (const float*)d_in[5];
    const float* ff1_w  = (const float*)d_in[6];
    const float* ff1_b  = (const float*)d_in[7];
    const float* ff2_w  = (const float*)d_in[8];
    const float* ff2_b  = (const float*)d_in[9];
    const float* ln2_g  = (const float*)d_in[10];
    const float* ln2_b  = (const float*)d_in[11];
    const float* w_fuse = (const float*)d_in[12];
    const float* bn_g   = (const float*)d_in[13];
    const float* bn_b   = (const float*)d_in[14];
    const float* bn_mean= (const float*)d_in[15];
    const float* bn_var = (const float*)d_in[16];
    float* out = (float*)d_out;

    const int SMEM_A = 46080;
    const int SMEM_B = SMB_BYTES;   // 70016
    cudaFuncSetAttribute(qkv_kernel, cudaFuncAttributeMaxDynamicSharedMemorySize, SMEM_A);
    cudaFuncSetAttribute(attn_ffn_kernel, cudaFuncAttributeMaxDynamicSharedMemorySize, SMEM_B);

    cvt_weights_kernel<<<512, 128>>>(wq, wk, wv, ff1_w, ff2_w, w_fuse);
    qkv_kernel<<<296, 256, SMEM_A>>>(x);

    dim3 grid(WDIM/64, HDIM/2, BATCH);
    attn_ffn_kernel<<<grid, 256, SMEM_B>>>(
        x, ln1_g, ln1_b, ff1_b, ff2_b,
        ln2_g, ln2_b, bn_g, bn_b, bn_mean, bn_var, out);
}

// round 16
// speedup vs baseline: 1.0796x; 1.0796x over previous
#include <cuda_runtime.h>
#include <cuda_fp16.h>

#define BATCH 4
#define HDIM 384
#define WDIM 384
#define NPIX (BATCH*HDIM*WDIM)

// fp16 q/k/v scratch
__device__ __half g_q[NPIX*64];
__device__ __half g_k[NPIX*64];
__device__ __half g_v[NPIX*64];
// fp16 weights, B-operand layout [n][k] padded to 72
__device__ __half g_wqkv_h[192*72];
__device__ __half g_ff1n[128*72];
__device__ __half g_ff2n[2*64*72];
__device__ __half g_wfusen[64*72];

__device__ __forceinline__ void mma_f16(float* d,
    unsigned a0, unsigned a1, unsigned a2, unsigned a3,
    unsigned b0, unsigned b1)
{
    asm volatile("mma.sync.aligned.m16n8k16.row.col.f32.f16.f16.f32 "
        "{%0,%1,%2,%3}, {%4,%5,%6,%7}, {%8,%9}, {%0,%1,%2,%3};"
        : "+f"(d[0]), "+f"(d[1]), "+f"(d[2]), "+f"(d[3])
        : "r"(a0), "r"(a1), "r"(a2), "r"(a3), "r"(b0), "r"(b1));
}

__device__ __forceinline__ unsigned sptr(const void* p) {
    return (unsigned)__cvta_generic_to_shared((void*)p);
}
__device__ __forceinline__ unsigned h2u(float a, float b) {
    __half2 h = __floats2half2_rn(a, b);
    return *(unsigned*)&h;
}
#define CP16(dst, src, sz) \
    asm volatile("cp.async.cg.shared.global [%0], [%1], 16, %2;" \
                 :: "r"(dst), "l"(src), "r"(sz))
#define CP_COMMIT asm volatile("cp.async.commit_group;" ::: "memory")
#define CP_WAIT0  asm volatile("cp.async.wait_group 0;"  ::: "memory")

// ---------------------------------------------------------------------------
// One-time weight prep: row-per-block decode
// ---------------------------------------------------------------------------
__global__ void __launch_bounds__(128) cvt_weights_kernel(
    const float* __restrict__ wq, const float* __restrict__ wk,
    const float* __restrict__ wv, const float* __restrict__ ff1_w,
    const float* __restrict__ ff2_w, const float* __restrict__ w_fuse)
{
    int r = blockIdx.x, k = threadIdx.x;
    if (k >= 72) return;
    float v = 0.f;
    __half* dst;
    if (r < 192) {
        if (k < 64) {
            if (r < 64)       v = wq[k*64 + r];
            else if (r < 128) v = wk[k*64 + r - 64];
            else              v = wv[k*64 + r - 128];
        }
        dst = g_wqkv_h + r*72;
    } else if (r < 320) {
        int n = r - 192;
        if (k < 64) v = ff1_w[k*128 + n];
        dst = g_ff1n + n*72;
    } else if (r < 448) {
        int q2 = r - 320;
        int P = q2 >> 6, n = q2 & 63;
        if (k < 64) v = ff2_w[(P*64 + k)*64 + n];
        dst = g_ff2n + q2*72;
    } else {
        int n = r - 448;
        if (k < 64) v = w_fuse[k*64 + n];
        dst = g_wfusen + n*72;
    }
    dst[k] = __float2half_rn(v);
}

// ---------------------------------------------------------------------------
// Kernel A: persistent qkv projection; epilogue via 4-lane register transpose
// so every store is a full 16B uint4 (100% write-sector efficiency).
// ---------------------------------------------------------------------------
#define NTILES 9216

__global__ void __launch_bounds__(256,2) qkv_kernel(const float* __restrict__ x)
{
    extern __shared__ char smc[];
    __half* ws  = (__half*)smc;
    __half* xs0 = (__half*)(smc + 27648);
    __half* xs1 = (__half*)(smc + 36864);
    const int tid = threadIdx.x;

    {
        const char* src = (const char*)g_wqkv_h;
        unsigned base = sptr(ws);
        for (int i = tid; i < 1728; i += 256) CP16(base + i*16, src + i*16, 16);
        CP_COMMIT;
    }

    int tile = blockIdx.x;
    const int stride = gridDim.x;

    float4 r[4];
    {
        const float4* xg = (const float4*)(x + (long)tile*64*64);
        #pragma unroll
        for (int j = 0; j < 4; j++) r[j] = xg[tid + 256*j];
    }
    CP_WAIT0;
    #pragma unroll
    for (int j = 0; j < 4; j++) {
        int i = tid + 256*j;
        int m = i >> 4, c4 = i & 15;
        int col = (4*c4) ^ ((m & 3) << 4);
        __half2* d = (__half2*)&xs0[m*72 + col];
        d[0] = __floats2half2_rn(r[j].x, r[j].y);
        d[1] = __floats2half2_rn(r[j].z, r[j].w);
    }
    __syncthreads();

    const int wid = tid >> 5, lane = tid & 31;
    const int gr = lane >> 2, tg = lane & 3;
    const int m0 = (wid >> 1) * 16;
    const int nb = (wid & 1) * 96;
    const unsigned* wsU = (const unsigned*)ws;
    const int mr = m0 + gr;
    const int sw = (mr & 3) << 3;

    int cur = 0;
    while (true) {
        int ntile = tile + stride;
        bool more = ntile < NTILES;
        if (more) {
            const float4* xg = (const float4*)(x + (long)ntile*64*64);
            #pragma unroll
            for (int j = 0; j < 4; j++) r[j] = xg[tid + 256*j];
        }

        const unsigned* xsU = (const unsigned*)(cur ? xs1 : xs0);
        float d[12][4];
        #pragma unroll
        for (int j = 0; j < 12; j++)
            #pragma unroll
            for (int c = 0; c < 4; c++) d[j][c] = 0.f;

        #pragma unroll
        for (int k0 = 0; k0 < 64; k0 += 16) {
            const int kc = k0 >> 1;
            unsigned a0 = xsU[mr*36       + ((kc+tg)   ^ sw)];
            unsigned a1 = xsU[mr*36 + 288 + ((kc+tg)   ^ sw)];
            unsigned a2 = xsU[mr*36       + ((kc+tg+4) ^ sw)];
            unsigned a3 = xsU[mr*36 + 288 + ((kc+tg+4) ^ sw)];
            #pragma unroll
            for (int j = 0; j < 12; j++) {
                int nn = nb + j*8;
                unsigned b0 = wsU[(nn+gr)*36 + kc+tg];
                unsigned b1 = wsU[(nn+gr)*36 + kc+tg+4];
                mma_f16(d[j], a0, a1, a2, a3, b0, b1);
            }
        }

        // ---- epilogue: per j-pair 4-lane transpose -> uint4 stores ----
        #pragma unroll
        for (int P = 0; P < 6; P++) {
            const int J = 2*P;
            unsigned x0 = h2u(d[J][0],   d[J][1]);    // (r0, cJ+2tg)
            unsigned x1 = h2u(d[J+1][0], d[J+1][1]);  // (r0, cJ+8+2tg)
            unsigned x2 = h2u(d[J][2],   d[J][3]);    // (r1, cJ+2tg)
            unsigned x3 = h2u(d[J+1][2], d[J+1][3]);  // (r1, cJ+8+2tg)
            unsigned t;
            t = (tg & 1) ? x0 : x1; t = __shfl_xor_sync(0xffffffffu, t, 1);
            if (tg & 1) x0 = t; else x1 = t;
            t = (tg & 1) ? x2 : x3; t = __shfl_xor_sync(0xffffffffu, t, 1);
            if (tg & 1) x2 = t; else x3 = t;
            t = (tg & 2) ? x0 : x2; t = __shfl_xor_sync(0xffffffffu, t, 2);
            if (tg & 2) x0 = t; else x2 = t;
            t = (tg & 2) ? x1 : x3; t = __shfl_xor_sync(0xffffffffu, t, 2);
            if (tg & 2) x1 = t; else x3 = t;
            // lane tg owns block: row = r0 or r1 (tg bit1), col = cJ or cJ+8 (tg bit0)
            int blk = nb + P*16 + (tg & 1)*8;
            __half* dst; int nn;
            if (blk < 64)       { dst = g_q; nn = blk; }
            else if (blk < 128) { dst = g_k; nn = blk - 64; }
            else                { dst = g_v; nn = blk - 128; }
            long m = (long)tile*64 + mr + ((tg & 2) ? 8 : 0);
            *(uint4*)&dst[m*64 + nn] = make_uint4(x0, x1, x2, x3);
        }

        if (!more) break;
        tile = ntile;
        __half* xsn = cur ? xs0 : xs1;
        #pragma unroll
        for (int j = 0; j < 4; j++) {
            int i = tid + 256*j;
            int m = i >> 4, c4 = i & 15;
            int col = (4*c4) ^ ((m & 3) << 4);
            __half2* dd = (__half2*)&xsn[m*72 + col];
            dd[0] = __floats2half2_rn(r[j].x, r[j].y);
            dd[1] = __floats2half2_rn(r[j].z, r[j].w);
        }
        cur ^= 1;
        __syncthreads();
    }
}

// ---------------------------------------------------------------------------
// Shared 128x32 (K=64) fp16 MMA GEMM body
// ---------------------------------------------------------------------------
__device__ __forceinline__ void gemm_64(const unsigned* aU, const unsigned* bU,
    int m0, int gr, int tg, int wn, float d[8][4])
{
    #pragma unroll
    for (int k0 = 0; k0 < 64; k0 += 16) {
        const int kc = k0 >> 1;
        unsigned a[2][4];
        #pragma unroll
        for (int t = 0; t < 2; t++) {
            int mr = m0 + 16*t + gr;
            int sw = (mr & 3) << 3;
            int base = mr*36;
            a[t][0] = aU[base       + ((kc+tg)   ^ sw)];
            a[t][1] = aU[base + 288 + ((kc+tg)   ^ sw)];
            a[t][2] = aU[base       + ((kc+tg+4) ^ sw)];
            a[t][3] = aU[base + 288 + ((kc+tg+4) ^ sw)];
        }
        #pragma unroll
        for (int j = 0; j < 4; j++) {
            int nn = wn*32 + j*8;
            unsigned b0 = bU[(nn+gr)*36 + kc+tg];
            unsigned b1 = bU[(nn+gr)*36 + kc+tg+4];
            #pragma unroll
            for (int t = 0; t < 2; t++)
                mma_f16(d[t*4+j], a[t][0], a[t][1], a[t][2], a[t][3], b0, b1);
        }
    }
}

// ---------------------------------------------------------------------------
// Kernel B (r14 verbatim). smem bytes (60800 total):
//   [0,38016)      halo half [264][72] (swizzled)
//     aliases: s_w [0,9216) | s_h [9216,27648)
//   [38016,40064)  s_sums f32 [128][4]
//   [40064,58496)  s_o half [128][72] (swizzled)
//   [58496,60800)  s_m fp32 (576)
// ---------------------------------------------------------------------------
#define SMB_BYTES 60800

__global__ void __launch_bounds__(256,3) attn_ffn_kernel(
    const float* __restrict__ x,
    const float* __restrict__ ln1_g, const float* __restrict__ ln1_b,
    const float* __restrict__ ff1_b,
    const float* __restrict__ ff2_b,
    const float* __restrict__ ln2_g, const float* __restrict__ ln2_b,
    const float* __restrict__ bn_g, const float* __restrict__ bn_b,
    const float* __restrict__ bn_mean, const float* __restrict__ bn_var,
    float* __restrict__ out)
{
    extern __shared__ char smc[];
    __half* s_halo = (__half*)smc;              // [264][72]
    __half* s_w    = (__half*)smc;              // [64][72]
    __half* s_h    = (__half*)(smc + 9216);     // [128][72]
    float*  s_sums = (float*)(smc + 38016);     // [128][4]
    __half* s_o    = (__half*)(smc + 40064);    // [128][72]
    float*  s_m    = (float*)(smc + 58496);

    const int tid = threadIdx.x;
    const int b  = blockIdx.z;
    const int y0 = blockIdx.y * 2;
    const int c0 = blockIdx.x * 64;

    // ---- issue k-halo cp.async ----
    #pragma unroll
    for (int r = 0; r < 4; r++) {
        const int gy = y0 + r - 1;
        const bool rowok = (unsigned)gy < HDIM;
        const __half* src = g_k + (((long)b*HDIM + gy)*WDIM + c0 - 1)*64;
        for (int idx = tid; idx < 528; idx += 256) {
            int j = idx >> 3, c8 = idx & 7;
            int gx = c0 + j - 1;
            int row = r*66 + j;
            int off = row*72 + ((c8*8) ^ ((row & 3) << 4));
            int sz = (rowok && (unsigned)gx < WDIM) ? 16 : 0;
            CP16(sptr(s_halo + off), src + j*64 + c8*8, sz);
        }
    }
    CP_COMMIT;

    if (tid < 64) {
        s_m[tid]        = ln1_g[tid];
        s_m[64 + tid]   = ln1_b[tid];
        s_m[128 + tid]  = ln2_g[tid];
        s_m[192 + tid]  = ln2_b[tid];
        s_m[384 + tid]  = ff2_b[tid];
        float sc = bn_g[tid] * rsqrtf(bn_var[tid] + 1e-3f);
        s_m[448 + tid]  = sc;
        s_m[512 + tid]  = bn_b[tid] - bn_mean[tid]*sc;
    } else if (tid < 192) {
        s_m[256 + (tid - 64)] = ff1_b[tid - 64];
    }

    const int p  = tid >> 2;
    const int hd = tid & 3;
    const long base0 = (((long)b*HDIM + y0)*WDIM + c0 + p)*64;
    const long base1 = base0 + WDIM*64;

    union HU { uint4 u[2]; __half2 h[8]; };
    HU q0h, q1h;
    q0h.u[0] = *(const uint4*)(g_q + base0 + hd*16);
    q0h.u[1] = *(const uint4*)(g_q + base0 + hd*16 + 8);
    q1h.u[0] = *(const uint4*)(g_q + base1 + hd*16);
    q1h.u[1] = *(const uint4*)(g_q + base1 + hd*16 + 8);
    CP_WAIT0;
    __syncthreads();

    // ---- scores: half2 accumulation, no max-sub ----
    float s0[9], s1[9];
    #pragma unroll
    for (int r = 0; r < 4; r++) {
        #pragma unroll
        for (int dx = 0; dx < 3; dx++) {
            int row = r*66 + p + dx;
            const __half* kp = &s_halo[row*72 + ((hd ^ (row & 3)) << 4)];
            HU bk;
            bk.u[0] = *(const uint4*)kp;
            bk.u[1] = *(const uint4*)(kp + 8);
            if (r < 3) {
                __half2 acc = __float2half2_rn(0.f);
                #pragma unroll
                for (int i = 0; i < 8; i++) acc = __hfma2(q0h.h[i], bk.h[i], acc);
                float2 f = __half22float2(acc);
                s0[r*3 + dx] = (f.x + f.y) * 0.25f;
            }
            if (r > 0) {
                __half2 acc = __float2half2_rn(0.f);
                #pragma unroll
                for (int i = 0; i < 8; i++) acc = __hfma2(q1h.h[i], bk.h[i], acc);
                float2 f = __half22float2(acc);
                s1[(r-1)*3 + dx] = (f.x + f.y) * 0.25f;
            }
        }
    }
    float sum0 = 0.f, sum1 = 0.f;
    #pragma unroll
    for (int o = 0; o < 9; o++) {
        s0[o] = __expf(s0[o]); sum0 += s0[o];
        s1[o] = __expf(s1[o]); sum1 += s1[o];
    }
    const float si0 = 1.f/sum0, si1 = 1.f/sum1;
    #pragma unroll
    for (int o = 0; o < 9; o++) { s0[o] *= si0; s1[o] *= si1; }

    __syncthreads();   // k-halo reads done

    // ---- issue v-halo cp.async ----
    #pragma unroll
    for (int r = 0; r < 4; r++) {
        const int gy = y0 + r - 1;
        const bool rowok = (unsigned)gy < HDIM;
        const __half* src = g_v + (((long)b*HDIM + gy)*WDIM + c0 - 1)*64;
        for (int idx = tid; idx < 528; idx += 256) {
            int j = idx >> 3, c8 = idx & 7;
            int gx = c0 + j - 1;
            int row = r*66 + j;
            int off = row*72 + ((c8*8) ^ ((row & 3) << 4));
            int sz = (rowok && (unsigned)gx < WDIM) ? 16 : 0;
            CP16(sptr(s_halo + off), src + j*64 + c8*8, sz);
        }
    }
    CP_COMMIT;

    float xr0[16], xr1[16];
    #pragma unroll
    for (int i = 0; i < 4; i++) {
        *(float4*)&xr0[4*i] = *(const float4*)(x + base0 + hd*16 + 4*i);
        *(float4*)&xr1[4*i] = *(const float4*)(x + base1 + hd*16 + 4*i);
    }
    CP_WAIT0;
    __syncthreads();

    // ---- weighted v sums: half2 ----
    __half2 a0h[8], a1h[8];
    #pragma unroll
    for (int i = 0; i < 8; i++) { a0h[i] = __float2half2_rn(0.f); a1h[i] = __float2half2_rn(0.f); }
    #pragma unroll
    for (int r = 0; r < 4; r++) {
        #pragma unroll
        for (int dx = 0; dx < 3; dx++) {
            int row = r*66 + p + dx;
            const __half* vp = &s_halo[row*72 + ((hd ^ (row & 3)) << 4)];
            HU bv;
            bv.u[0] = *(const uint4*)vp;
            bv.u[1] = *(const uint4*)(vp + 8);
            if (r < 3) {
                __half2 w = __half2half2(__float2half_rn(s0[r*3 + dx]));
                #pragma unroll
                for (int i = 0; i < 8; i++) a0h[i] = __hfma2(w, bv.h[i], a0h[i]);
            }
            if (r > 0) {
                __half2 w = __half2half2(__float2half_rn(s1[(r-1)*3 + dx]));
                #pragma unroll
                for (int i = 0; i < 8; i++) a1h[i] = __hfma2(w, bv.h[i], a1h[i]);
            }
        }
    }

    // ---- LN1 (+residual) fp32; fp16 into swizzled s_o ----
    #pragma unroll
    for (int rr = 0; rr < 2; rr++) {
        __half2* ah = rr ? a1h : a0h;
        float* xv = rr ? xr1 : xr0;
        float av[16];
        #pragma unroll
        for (int i = 0; i < 8; i++) {
            float2 f = __half22float2(ah[i]);
            av[2*i] = f.x; av[2*i+1] = f.y;
        }
        float m1 = 0.f, m2 = 0.f;
        #pragma unroll
        for (int dd = 0; dd < 16; dd++) {
            av[dd] += xv[dd];
            m1 += av[dd];
            m2 = fmaf(av[dd], av[dd], m2);
        }
        m1 += __shfl_xor_sync(0xffffffff, m1, 1);
        m2 += __shfl_xor_sync(0xffffffff, m2, 1);
        m1 += __shfl_xor_sync(0xffffffff, m1, 2);
        m2 += __shfl_xor_sync(0xffffffff, m2, 2);
        const float mean = m1 * (1.f/64.f);
        const float var  = m2 * (1.f/64.f) - mean*mean;
        const float rstd = rsqrtf(var + 1e-3f);
        int row = rr*64 + p;
        __half2* dst = (__half2*)&s_o[row*72 + ((hd ^ (row & 3)) << 4)];
        #pragma unroll
        for (int i = 0; i < 4; i++) {
            const int c = hd*16 + 4*i;
            float w0 = (av[4*i+0] - mean)*rstd*s_m[c+0] + s_m[64+c+0];
            float w1 = (av[4*i+1] - mean)*rstd*s_m[c+1] + s_m[64+c+1];
            float w2 = (av[4*i+2] - mean)*rstd*s_m[c+2] + s_m[64+c+2];
            float w3 = (av[4*i+3] - mean)*rstd*s_m[c+3] + s_m[64+c+3];
            dst[2*i]   = __floats2half2_rn(w0, w1);
            dst[2*i+1] = __floats2half2_rn(w2, w3);
        }
    }
    __syncthreads();   // halo dead; LN1 visible

    const int wid = tid >> 5, lane = tid & 31;
    const int gr = lane >> 2, tg = lane & 3;
    const int m0 = (wid >> 1) * 32;
    const int wn = wid & 1;
    const unsigned* soU = (const unsigned*)s_o;
    const unsigned* shU = (const unsigned*)s_h;
    const unsigned* swU = (const unsigned*)s_w;

    // ---- fused FFN: per half P: GEMM1 -> s_h -> GEMM2 accumulate ----
    float d2[8][4];
    #pragma unroll
    for (int j = 0; j < 8; j++)
        #pragma unroll
        for (int c = 0; c < 4; c++) d2[j][c] = 0.f;

    #pragma unroll
    for (int P = 0; P < 2; P++) {
        {
            const char* src = (const char*)g_ff1n + P*9216;
            unsigned base = sptr(s_w);
            for (int i = tid; i < 576; i += 256) CP16(base + i*16, src + i*16, 16);
            CP_COMMIT;
        }
        CP_WAIT0;
        __syncthreads();
        float d1[8][4];
        #pragma unroll
        for (int j = 0; j < 8; j++)
            #pragma unroll
            for (int c = 0; c < 4; c++) d1[j][c] = 0.f;
        gemm_64(soU, swU, m0, gr, tg, wn, d1);
        __syncthreads();
        {
            const char* src = (const char*)g_ff2n + P*9216;
            unsigned base = sptr(s_w);
            for (int i = tid; i < 576; i += 256) CP16(base + i*16, src + i*16, 16);
            CP_COMMIT;
        }
        #pragma unroll
        for (int t = 0; t < 2; t++) {
            #pragma unroll
            for (int j = 0; j < 4; j++) {
                int nl = wn*32 + j*8 + 2*tg;
                int ng = P*64 + nl;
                int mr = m0 + 16*t + gr;
                float bb0 = s_m[256 + ng], bb1 = s_m[256 + ng + 1];
                int sw4 = (mr & 3) << 4;
                *(__half2*)&s_h[mr*72 + (nl ^ sw4)] = __floats2half2_rn(
                    fmaxf(d1[t*4+j][0] + bb0, 0.f), fmaxf(d1[t*4+j][1] + bb1, 0.f));
                *(__half2*)&s_h[(mr+8)*72 + (nl ^ sw4)] = __floats2half2_rn(
                    fmaxf(d1[t*4+j][2] + bb0, 0.f), fmaxf(d1[t*4+j][3] + bb1, 0.f));
            }
        }
        CP_WAIT0;
        __syncthreads();
        gemm_64(shU, swU, m0, gr, tg, wn, d2);
        __syncthreads();
    }

    {   // stage fuse weights (overlaps epilogue + LN2)
        const char* src = (const char*)g_wfusen;
        unsigned base = sptr(s_w);
        for (int i = tid; i < 576; i += 256) CP16(base + i*16, src + i*16, 16);
        CP_COMMIT;
    }

    // ---- epilogue + warp-level LN2 ----
    float rs[4], rq[4];
    #pragma unroll
    for (int i = 0; i < 4; i++) { rs[i] = 0.f; rq[i] = 0.f; }
    #pragma unroll
    for (int t = 0; t < 2; t++) {
        #pragma unroll
        for (int j = 0; j < 4; j++) {
            int n = wn*32 + j*8 + 2*tg;
            int mr = m0 + 16*t + gr;
            int sw4 = (mr & 3) << 4;
            float bb0 = s_m[384 + n], bb1 = s_m[384 + n + 1];
            float2 o0 = __half22float2(*(__half2*)&s_o[mr*72 + (n ^ sw4)]);
            float2 o1 = __half22float2(*(__half2*)&s_o[(mr+8)*72 + (n ^ sw4)]);
            float v0 = o0.x + d2[t*4+j][0] + bb0;
            float v1 = o0.y + d2[t*4+j][1] + bb1;
            float v2 = o1.x + d2[t*4+j][2] + bb0;
            float v3 = o1.y + d2[t*4+j][3] + bb1;
            d2[t*4+j][0] = v0; d2[t*4+j][1] = v1;
            d2[t*4+j][2] = v2; d2[t*4+j][3] = v3;
            rs[2*t]   += v0 + v1;
            rq[2*t]   = fmaf(v0, v0, fmaf(v1, v1, rq[2*t]));
            rs[2*t+1] += v2 + v3;
            rq[2*t+1] = fmaf(v2, v2, fmaf(v3, v3, rq[2*t+1]));
        }
    }
    #pragma unroll
    for (int i = 0; i < 4; i++) {
        rs[i] += __shfl_xor_sync(0xffffffff, rs[i], 1);
        rq[i] += __shfl_xor_sync(0xffffffff, rq[i], 1);
        rs[i] += __shfl_xor_sync(0xffffffff, rs[i], 2);
        rq[i] += __shfl_xor_sync(0xffffffff, rq[i], 2);
    }
    if (tg == 0) {
        #pragma unroll
        for (int i = 0; i < 4; i++) {
            int row = m0 + 16*(i >> 1) + 8*(i & 1) + gr;
            *(float2*)&s_sums[row*4 + wn*2] = make_float2(rs[i], rq[i]);
        }
    }
    __syncthreads();

    float mean[4], rstd[4];
    #pragma unroll
    for (int i = 0; i < 4; i++) {
        int row = m0 + 16*(i >> 1) + 8*(i & 1) + gr;
        float4 s4 = *(const float4*)&s_sums[row*4];
        float mn = (s4.x + s4.z) * (1.f/64.f);
        float vr = (s4.y + s4.w) * (1.f/64.f) - mn*mn;
        mean[i] = mn;
        rstd[i] = rsqrtf(vr + 1e-3f);
    }
    #pragma unroll
    for (int t = 0; t < 2; t++) {
        #pragma unroll
        for (int j = 0; j < 4; j++) {
            int n = wn*32 + j*8 + 2*tg;
            int mr = m0 + 16*t + gr;
            int sw4 = (mr & 3) << 4;
            float g0 = s_m[128 + n], g1 = s_m[128 + n + 1];
            float e0 = s_m[192 + n], e1 = s_m[192 + n + 1];
            int i0 = 2*t, i1 = 2*t + 1;
            *(__half2*)&s_o[mr*72 + (n ^ sw4)] = __floats2half2_rn(
                (d2[t*4+j][0] - mean[i0])*rstd[i0]*g0 + e0,
                (d2[t*4+j][1] - mean[i0])*rstd[i0]*g1 + e1);
            *(__half2*)&s_o[(mr+8)*72 + (n ^ sw4)] = __floats2half2_rn(
                (d2[t*4+j][2] - mean[i1])*rstd[i1]*g0 + e0,
                (d2[t*4+j][3] - mean[i1])*rstd[i1]*g1 + e1);
        }
    }
    CP_WAIT0;
    __syncthreads();

    // ---- GEMM3: fuse conv + BN + relu, direct global store ----
    {
        float d3[8][4];
        #pragma unroll
        for (int j = 0; j < 8; j++)
            #pragma unroll
            for (int c = 0; c < 4; c++) d3[j][c] = 0.f;
        gemm_64(soU, swU, m0, gr, tg, wn, d3);
        #pragma unroll
        for (int t = 0; t < 2; t++) {
            #pragma unroll
            for (int j = 0; j < 4; j++) {
                int n = wn*32 + j*8 + 2*tg;
                int mr = m0 + 16*t + gr;
                int ry = mr >> 6, mx = mr & 63;
                float sc0 = s_m[448 + n], sc1 = s_m[448 + n + 1];
                float sh0 = s_m[512 + n], sh1 = s_m[512 + n + 1];
                float* ob0 = out + ((b*HDIM + y0 + ry)*WDIM + c0 + mx)*64;
                float* ob1 = out + ((b*HDIM + y0 + ry)*WDIM + c0 + mx + 8)*64;
                *(float2*)&ob0[n] = make_float2(
                    fmaxf(d3[t*4+j][0]*sc0 + sh0, 0.f), fmaxf(d3[t*4+j][1]*sc1 + sh1, 0.f));
                *(float2*)&ob1[n] = make_float2(
                    fmaxf(d3[t*4+j][2]*sc0 + sh0, 0.f), fmaxf(d3[t*4+j][3]*sc1 + sh1, 0.f));
            }
        }
    }
}

extern "C" void kernel_launch(void* const* d_in, const int* in_sizes, int n_in,
                              void* d_out, int out_size)
{
    const float* x      = (const float*)d_in[0];
    const float* wq     = (const float*)d_in[1];
    const float* wk     = (const float*)d_in[2];
    const float* wv     = (const float*)d_in[3];
    const float* ln1_g  = (const float*)d_in[4];
    const float* ln1_b  = (const float*)d_in[5];
    const float* ff1_w  = (const float*)d_in[6];
    const float* ff1_b  = (const float*)d_in[7];
    const float* ff2_w  = (const float*)d_in[8];
    const float* ff2_b  = (const float*)d_in[9];
    const float* ln2_g  = (const float*)d_in[10];
    const float* ln2_b  = (const float*)d_in[11];
    const float* w_fuse = (const float*)d_in[12];
    const float* bn_g   = (const float*)d_in[13];
    const float* bn_b   = (const float*)d_in[14];
    const float* bn_mean= (const float*)d_in[15];
    const float* bn_var = (const float*)d_in[16];
    float* out = (float*)d_out;

    const int SMEM_A = 46080;
    const int SMEM_B = SMB_BYTES;   // 60800
    cudaFuncSetAttribute(qkv_kernel, cudaFuncAttributeMaxDynamicSharedMemorySize, SMEM_A);
    cudaFuncSetAttribute(attn_ffn_kernel, cudaFuncAttributeMaxDynamicSharedMemorySize, SMEM_B);

    cvt_weights_kernel<<<512, 128>>>(wq, wk, wv, ff1_w, ff2_w, w_fuse);
    qkv_kernel<<<296, 256, SMEM_A>>>(x);

    dim3 grid(WDIM/64, HDIM/2, BATCH);
    attn_ffn_kernel<<<grid, 256, SMEM_B>>>(
        x, ln1_g, ln1_b, ff1_b, ff2_b,
        ln2_g, ln2_b, bn_g, bn_b, bn_mean, bn_var, out);
}